// round 6
// baseline (speedup 1.0000x reference)
#include <cuda_runtime.h>
#include <math.h>

#define DINLINE __device__ __forceinline__

// ---------------- problem constants ----------------
#define Bb 8
#define Hh 128
#define Ww 128
#define Cc 96
#define Mm 192
#define SPEC (128*65)
#define INV_HW (1.0f/16384.0f)

// ---------------- device scratch ----------------
__device__ float  g_xpre[(size_t)Bb*Mm*Hh*Ww];     // reused in-place for xsp
__device__ float2 g_filt[(size_t)3*Mm*SPEC];       // resized filters (BR h order)
__device__ float2 g_tmp[(size_t)48*65*Mm];         // separable-resize intermediate
__device__ float  g_r[Bb*3*Mm];
__device__ float  g_stats[Bb*144];

extern __shared__ __align__(16) char SMEM[];

// ---------------- helpers ----------------
DINLINE int br7(int p){ return (int)(__brev((unsigned)p)>>25); }
DINLINE float2 cmulf(float2 a, float2 b){ return make_float2(a.x*b.x - a.y*b.y, a.x*b.y + a.y*b.x); }
DINLINE float2 f2add(float2 a,float2 b){ return make_float2(a.x+b.x, a.y+b.y); }
DINLINE float2 f2sub(float2 a,float2 b){ return make_float2(a.x-b.x, a.y-b.y); }
DINLINE float2 shflx(float2 v,int m){
    v.x = __shfl_xor_sync(0xffffffffu, v.x, m);
    v.y = __shfl_xor_sync(0xffffffffu, v.y, m);
    return v;
}

// Forward DIF 128-pt FFT: natural input at p=j*32+lane -> X[br7(p)] at p.
DINLINE void fft128_dif(float2 z[4], const float2* tw, int lane){
    #pragma unroll
    for(int j=0;j<2;j++){
        int k=j*32+lane;
        float2 u=z[j], v=z[j+2];
        z[j]=f2add(u,v);
        z[j+2]=cmulf(f2sub(u,v), tw[k]);
    }
    {
        float2 w=tw[2*lane];
        float2 u=z[0],v=z[1];
        z[0]=f2add(u,v); z[1]=cmulf(f2sub(u,v),w);
        u=z[2]; v=z[3];
        z[2]=f2add(u,v); z[3]=cmulf(f2sub(u,v),w);
    }
    #pragma unroll
    for(int d=16; d>=1; d>>=1){
        int k=lane&(d-1);
        float2 w=tw[k*(64/d)];
        bool up=(lane&d)!=0;
        #pragma unroll
        for(int j=0;j<4;j++){
            float2 o=shflx(z[j],d);
            float2 r;
            if(up) r=cmulf(make_float2(o.x - z[j].x, o.y - z[j].y), w);
            else   r=make_float2(z[j].x+o.x, z[j].y+o.y);
            z[j]=r;
        }
    }
}

// DIT 128-pt FFT: bit-reversed input at p -> natural output at p.
template<bool CONJ>
DINLINE void fft128_dit(float2 z[4], const float2* tw, int lane){
    #pragma unroll
    for(int d=1; d<=16; d<<=1){
        int k=lane&(d-1);
        float2 w=tw[k*(64/d)];
        if(CONJ) w.y=-w.y;
        bool up=(lane&d)!=0;
        #pragma unroll
        for(int j=0;j<4;j++){
            float2 o=shflx(z[j],d);
            float2 r;
            if(up){
                float2 t=cmulf(w, z[j]);
                r=make_float2(o.x-t.x, o.y-t.y);
            } else {
                float2 t=cmulf(w, o);
                r=make_float2(z[j].x+t.x, z[j].y+t.y);
            }
            z[j]=r;
        }
    }
    {
        float2 w=tw[2*lane]; if(CONJ) w.y=-w.y;
        float2 t=cmulf(w,z[1]); float2 u=z[0];
        z[0]=f2add(u,t); z[1]=f2sub(u,t);
        t=cmulf(w,z[3]); u=z[2];
        z[2]=f2add(u,t); z[3]=f2sub(u,t);
    }
    #pragma unroll
    for(int j=0;j<2;j++){
        int k=j*32+lane;
        float2 w=tw[k]; if(CONJ) w.y=-w.y;
        float2 t=cmulf(w,z[j+2]); float2 u=z[j];
        z[j]=f2add(u,t);
        z[j+2]=f2sub(u,t);
    }
}

// ---------------- bicubic resize taps (match reference) ----------------
DINLINE double cubicw(double t){
    t = fabs(t);
    const double a = -0.75;
    if(t <= 1.0) return ((a+2.0)*t - (a+3.0))*t*t + 1.0;
    if(t <  2.0) return a*(((t-5.0)*t+8.0)*t-4.0);
    return 0.0;
}
DINLINE void taps4(int j, int oldn, int newn, int* idx, float* wt){
    double s = (newn > 1) ? (double)j * (double)(oldn-1) / (double)(newn-1) : 0.0;
    int f = (int)floor(s);
    #pragma unroll
    for(int k=0;k<4;k++){
        int kk = f + k - 1;
        idx[k] = min(max(kk, 0), oldn-1);
        wt[k]  = (float)cubicw(s - (double)kk);
    }
}

// scale tables
__constant__ int c_SH[3]={16,8,24};
__constant__ int c_SW[3]={9,4,13};
__constant__ int c_RB[3]={0,16,24};   // row base in g_tmp

// ---------------- k_filt1: W-resize, one block per source row ----------------
__global__ void __launch_bounds__(256) k_filt1(const float* __restrict__ cw0,
                                               const float* __restrict__ cw1,
                                               const float* __restrict__ cw2){
    __shared__ int   widx[65][4];
    __shared__ float wwt [65][4];
    __shared__ float2 rowb[13*Mm];    // max ow=13
    int r = blockIdx.x;               // 0..47
    int s = (r<16)?0:((r<24)?1:2);
    int ih = r - c_RB[s];
    int ow = c_SW[s];
    const float* cws = (s==0)?cw0:((s==1)?cw1:cw2);
    int tid=threadIdx.x;
    if(tid<65) taps4(tid, ow, 65, widx[tid], wwt[tid]);
    const float2* src = (const float2*)(cws) + (size_t)ih*ow*Mm;
    for(int i=tid;i<ow*Mm;i+=256) rowb[i]=src[i];
    __syncthreads();
    float2* dst = g_tmp + (size_t)r*65*Mm;
    for(int e=tid;e<65*Mm;e+=256){
        int w=e/Mm, m=e%Mm;
        float ax=0.f, ay=0.f;
        #pragma unroll
        for(int a=0;a<4;a++){
            float wg=wwt[w][a];
            float2 v=rowb[widx[w][a]*Mm+m];
            ax+=wg*v.x; ay+=wg*v.y;
        }
        dst[e]=make_float2(ax,ay);
    }
}

// ---------------- k_filt2: H-resize + transpose into [s][m][BRh*65+w] ----------------
__global__ void __launch_bounds__(128) k_filt2(){
    __shared__ int   hidx[4];
    __shared__ float hwt [4];
    __shared__ float2 tile[48*65];    // [mm][w]
    int bid=blockIdx.x;               // 3*128*4
    int s  = bid/512;
    int rem= bid%512;
    int hq = rem/4;
    int m0 = (rem%4)*48;
    int tid=threadIdx.x;
    if(tid==0){
        int id[4]; float wt[4];
        taps4(hq, c_SH[s], 128, id, wt);
        #pragma unroll
        for(int a=0;a<4;a++){ hidx[a]=id[a]; hwt[a]=wt[a]; }
    }
    __syncthreads();
    const float2* base = g_tmp + (size_t)c_RB[s]*65*Mm;
    for(int e=tid;e<65*48;e+=128){
        int w=e/48, mm=e%48;
        int m=m0+mm;
        float ax=0.f, ay=0.f;
        #pragma unroll
        for(int a=0;a<4;a++){
            float2 v=base[(size_t)hidx[a]*65*Mm + w*Mm + m];
            ax+=hwt[a]*v.x; ay+=hwt[a]*v.y;
        }
        tile[mm*65+w]=make_float2(ax,ay);
    }
    __syncthreads();
    int hb=br7(hq);
    for(int e=tid;e<48*65;e+=128){
        int mm=e/65, w=e%65;
        g_filt[(size_t)(s*Mm+m0+mm)*SPEC + hb*65 + w]=tile[mm*65+w];
    }
}

// ---------------- k_zero ----------------
__global__ void k_zero(){
    for(int i=threadIdx.x;i<Bb*144;i+=blockDim.x) g_stats[i]=0.f;
}

// ---------------- k_pw1: fused pwconv1+Soa + routing stats (512 thr, float2 LDS) ----------------
// rows padded to 98 floats (49 float2, odd float2-stride => conflict-free LDS.64)
#define PW1_XS   0
#define PW1_WS   (PW1_XS+128*98)
#define PW1_SWS  (PW1_WS+192*98)
#define PW1_BNP  (PW1_SWS+48*98)
#define PW1_RED  (PW1_BNP+96)
#define PW1_TOT  (PW1_RED+48*33)
__global__ void __launch_bounds__(512) k_pw1(const float* __restrict__ x,
                                             const float* __restrict__ w1,
                                             const float* __restrict__ s1,
                                             const float* __restrict__ b1,
                                             const float* __restrict__ spw,
                                             const float* __restrict__ bng,
                                             const float* __restrict__ bnb,
                                             const float* __restrict__ bnm,
                                             const float* __restrict__ bnv){
    float* S=(float*)SMEM;
    float* xs  = S+PW1_XS;
    float* ws  = S+PW1_WS;
    float* sws = S+PW1_SWS;
    float* bnp = S+PW1_BNP;
    float* red = S+PW1_RED;
    int tid=threadIdx.x;
    int b=blockIdx.y, pix0=blockIdx.x*128;
    const float2* xb2 = (const float2*)(x + ((size_t)b*16384 + pix0)*96);
    // copy with float2 (96 even, 98 even -> aligned)
    for(int i=tid;i<128*48;i+=512){ int p=i/48,c=i%48; ((float2*)(xs+p*98))[c]=xb2[i]; }
    for(int i=tid;i<192*48;i+=512){ int mm=i/48,c=i%48; ((float2*)(ws+mm*98))[c]=((const float2*)w1)[i]; }
    for(int i=tid;i<48*48;i+=512){ int sc=i/48,c=i%48; ((float2*)(sws+sc*98))[c]=((const float2*)spw)[i]; }
    if(tid<48){
        float sc=rsqrtf(bnv[tid]+1e-5f)*bng[tid];
        bnp[tid]=sc;
        bnp[48+tid]=bnb[tid]-bnm[tid]*sc;
    }
    __syncthreads();
    int tx=tid&15, ty=tid>>4;    // ty 0..31 -> 4 pixels each
    const float2* xs2 = (const float2*)xs;
    const float2* ws2 = (const float2*)ws;
    const float2* sws2= (const float2*)sws;
    float acc[4][12];
    float acc2[4][3];
    #pragma unroll
    for(int i=0;i<4;i++){
        #pragma unroll
        for(int j=0;j<12;j++) acc[i][j]=0.f;
        #pragma unroll
        for(int j=0;j<3;j++) acc2[i][j]=0.f;
    }
    #pragma unroll 2
    for(int k2=0;k2<48;k2++){
        float2 xv[4], wv[12], wv2[3];
        #pragma unroll
        for(int i=0;i<4;i++) xv[i]=xs2[(ty+32*i)*49+k2];
        #pragma unroll
        for(int j=0;j<12;j++) wv[j]=ws2[(tx+16*j)*49+k2];
        #pragma unroll
        for(int j=0;j<3;j++) wv2[j]=sws2[(tx*3+j)*49+k2];
        #pragma unroll
        for(int i=0;i<4;i++){
            #pragma unroll
            for(int j=0;j<12;j++){ acc[i][j]+=xv[i].x*wv[j].x; acc[i][j]+=xv[i].y*wv[j].y; }
            #pragma unroll
            for(int j=0;j<3;j++){ acc2[i][j]+=xv[i].x*wv2[j].x; acc2[i][j]+=xv[i].y*wv2[j].y; }
        }
    }
    // sctx partials
    #pragma unroll
    for(int j=0;j<3;j++){
        int sc=tx*3+j;
        float scale=bnp[sc], shift=bnp[48+sc];
        float ssum=0.f;
        #pragma unroll
        for(int i=0;i<4;i++) ssum+=fmaxf(acc2[i][j]*scale+shift,0.f);
        red[sc*33+ty]=ssum;
    }
    // gctx
    float gsum=0.f;
    if(tid<96){
        #pragma unroll 4
        for(int p=0;p<128;p++) gsum+=xs[p*98+tid];
    }
    float scb=*s1, bib=*b1;
    __syncthreads();
    if(tid<96) atomicAdd(&g_stats[b*144+tid], gsum);
    if(tid<48){
        float ssum=0.f;
        #pragma unroll
        for(int t=0;t<32;t++) ssum+=red[tid*33+t];
        atomicAdd(&g_stats[b*144+96+tid], ssum);
    }
    float* outs = S;          // reuse: 192*129 = 24768 < PW1_TOT
    #pragma unroll
    for(int i=0;i<4;i++){
        int p=ty+32*i;
        #pragma unroll
        for(int j=0;j<12;j++){
            int mm=tx+16*j;
            float r=fmaxf(acc[i][j],0.f);
            outs[mm*129+p]=scb*r*r+bib;
        }
    }
    __syncthreads();
    float* op = g_xpre + (size_t)b*Mm*16384 + pix0;
    for(int i=tid;i<192*128;i+=512){
        int mm=i>>7, p=i&127;
        op[(size_t)mm*16384+p]=outs[mm*129+p];
    }
}

// ---------------- k_mlp ----------------
#define MLP_SF   0
#define MLP_FC1  (8*145)
#define MLP_HM   (MLP_FC1+36*145)
#define MLP_FC2  (MLP_HM+8*37)
#define MLP_TOT  (MLP_FC2+576*37)
__global__ void __launch_bounds__(512) k_mlp(const float* __restrict__ fc1,
                                             const float* __restrict__ fc2,
                                             const float* __restrict__ msc,
                                             const float* __restrict__ mbi){
    float* S=(float*)SMEM;
    float* sf  = S+MLP_SF;
    float* f1s = S+MLP_FC1;
    float* hm  = S+MLP_HM;
    float* f2s = S+MLP_FC2;
    int tid=threadIdx.x;
    for(int i=tid;i<8*144;i+=512){ int b=i/144,k=i%144; sf[b*145+k]=g_stats[i]*(1.f/16384.f); }
    for(int i=tid;i<36*144;i+=512){ int j=i/144,k=i%144; f1s[j*145+k]=fc1[i]; }
    for(int i=tid;i<576*36;i+=512){ int j=i/36,k=i%36; f2s[j*37+k]=fc2[i]; }
    __syncthreads();
    if(tid<288){
        int b=tid/36, j=tid%36;
        float a=0.f;
        #pragma unroll 8
        for(int k=0;k<144;k++) a+=sf[b*145+k]*f1s[j*145+k];
        float r=fmaxf(a,0.f);
        hm[b*37+j]=(*msc)*r*r + (*mbi);
    }
    __syncthreads();
    for(int idx=tid; idx<8*Mm; idx+=512){
        int b=idx/Mm, m=idx%Mm;
        float lg[3];
        #pragma unroll
        for(int s=0;s<3;s++){
            float a=0.f;
            const float* f2=f2s+(size_t)(s*Mm+m)*37;
            #pragma unroll
            for(int k=0;k<36;k++) a+=hm[b*37+k]*f2[k];
            lg[s]=a;
        }
        float mx=fmaxf(lg[0],fmaxf(lg[1],lg[2]));
        float e0=expf(lg[0]-mx), e1=expf(lg[1]-mx), e2=expf(lg[2]-mx);
        float inv=1.f/(e0+e1+e2);
        g_r[(b*3+0)*Mm+m]=e0*inv;
        g_r[(b*3+1)*Mm+m]=e1*inv;
        g_r[(b*3+2)*Mm+m]=e2*inv;
    }
}

// ---------------- k_fft (512 thr) ----------------
__global__ void __launch_bounds__(512) k_fft(){
    float2* sh=(float2*)SMEM;
    float2* sm = sh;                 // 8320
    float2* tmpAll = sh + SPEC;      // 16*128
    float2* tw = sh + SPEC + 2048;   // 64
    int tid=threadIdx.x, lane=tid&31, wid=tid>>5;   // 16 warps
    int bm=blockIdx.x;
    int b=bm/Mm, m=bm%Mm;
    float* plane = g_xpre + (size_t)bm*16384;
    if(tid<64){
        float s,c;
        sincospif((float)tid*(1.0f/64.0f), &s, &c);
        tw[tid]=make_float2(c,-s);
    }
    __syncthreads();
    float2* tmp = tmpAll + wid*128;
    // Phase A: forward row rFFTs
    for(int pr=wid; pr<64; pr+=16){
        int ra=2*pr, rb=ra+1;
        float2 z[4];
        #pragma unroll
        for(int j=0;j<4;j++){
            int p=j*32+lane, q=br7(p);
            z[j]=make_float2(plane[ra*128+q], plane[rb*128+q]);
        }
        fft128_dit<false>(z,tw,lane);
        #pragma unroll
        for(int j=0;j<4;j++) tmp[j*32+lane]=z[j];
        __syncwarp();
        #pragma unroll
        for(int t=0;t<2;t++){
            int k=t*32+lane;
            float2 Zk=tmp[k], Zc=tmp[(128-k)&127];
            sm[ra*65+k]=make_float2(0.5f*(Zk.x+Zc.x), 0.5f*(Zk.y-Zc.y));
            sm[rb*65+k]=make_float2(0.5f*(Zk.y+Zc.y), 0.5f*(Zc.x-Zk.x));
        }
        if(lane==0){
            float2 Zk=tmp[64];
            sm[ra*65+64]=make_float2(Zk.x,0.f);
            sm[rb*65+64]=make_float2(Zk.y,0.f);
        }
        __syncwarp();
    }
    __syncthreads();
    // Phase B: forward column FFTs (natural -> BR h)
    for(int col=wid; col<65; col+=16){
        float2 z[4];
        #pragma unroll
        for(int j=0;j<4;j++) z[j]=sm[(j*32+lane)*65+col];
        fft128_dif(z,tw,lane);
        #pragma unroll
        for(int j=0;j<4;j++) sm[(j*32+lane)*65+col]=z[j];
    }
    __syncthreads();
    // Phase C: routed filter multiply
    {
        float r0=g_r[(b*3+0)*Mm+m], r1=g_r[(b*3+1)*Mm+m], r2=g_r[(b*3+2)*Mm+m];
        const float2* f0=g_filt + (size_t)(0*Mm+m)*SPEC;
        const float2* f1=g_filt + (size_t)(1*Mm+m)*SPEC;
        const float2* f2=g_filt + (size_t)(2*Mm+m)*SPEC;
        for(int e=tid;e<SPEC;e+=512){
            float2 a=f0[e], bb=f1[e], c=f2[e];
            float2 comb=make_float2(a.x*r0+bb.x*r1+c.x*r2, a.y*r0+bb.y*r1+c.y*r2);
            sm[e]=cmulf(sm[e],comb);
        }
    }
    __syncthreads();
    // Phase D: inverse column FFTs
    for(int col=wid; col<65; col+=16){
        float2 z[4];
        #pragma unroll
        for(int j=0;j<4;j++) z[j]=sm[(j*32+lane)*65+col];
        fft128_dit<true>(z,tw,lane);
        #pragma unroll
        for(int j=0;j<4;j++) sm[(j*32+lane)*65+col]=z[j];
    }
    __syncthreads();
    // Phase E: inverse row rFFTs
    for(int pr=wid; pr<64; pr+=16){
        int ra=2*pr, rb=ra+1;
        float2 z[4];
        #pragma unroll
        for(int j=0;j<4;j++){
            int p=j*32+lane, k=br7(p);
            float2 zz;
            if(k<=64){
                float2 a=sm[ra*65+k], bb=sm[rb*65+k];
                if(k==0||k==64){ a.y=0.f; bb.y=0.f; }
                zz=make_float2(a.x-bb.y, a.y+bb.x);
            } else {
                int kk=128-k;
                float2 a=sm[ra*65+kk], bb=sm[rb*65+kk];
                zz=make_float2(a.x+bb.y, bb.x-a.y);
            }
            z[j]=zz;
        }
        fft128_dit<true>(z,tw,lane);
        #pragma unroll
        for(int j=0;j<4;j++){
            int p=j*32+lane;
            plane[ra*128+p]=z[j].x*INV_HW;
            plane[rb*128+p]=z[j].y*INV_HW;
        }
    }
}

// ---------------- k_pw2 (512 thr, k-major float2 LDS) ----------------
// As[p][194] (k-major), w2s[c][194]; 194 words = 97 float2 (odd) -> conflict-free
#define PW2_AS   0
#define PW2_W2   (PW2_AS+128*194)
#define PW2_TOT  (PW2_W2+96*194)
__global__ void __launch_bounds__(512) k_pw2(const float* __restrict__ w2,
                                             float* __restrict__ out){
    float* S=(float*)SMEM;
    float* As  = S+PW2_AS;
    float* w2s = S+PW2_W2;
    int tid=threadIdx.x;
    int b=blockIdx.y, pix0=blockIdx.x*128;
    const float* ap = g_xpre + (size_t)b*Mm*16384 + pix0;
    // transpose-load: read coalesced over p for each mm, write strided (2-way conflict, ok)
    for(int i=tid;i<192*128;i+=512){
        int mm=i>>7, p=i&127;
        As[p*194+mm]=ap[(size_t)mm*16384+p];
    }
    for(int i=tid;i<96*96;i+=512){
        int c=i/96, k2=i%96;
        ((float2*)(w2s+c*194))[k2]=((const float2*)w2)[c*96+k2];
    }
    __syncthreads();
    int tx=tid&15, ty=tid>>4;    // ty 0..31
    const float2* As2 =(const float2*)As;
    const float2* w2s2=(const float2*)w2s;
    float acc[4][6];
    #pragma unroll
    for(int i=0;i<4;i++)
        #pragma unroll
        for(int j=0;j<6;j++) acc[i][j]=0.f;
    #pragma unroll 2
    for(int k2=0;k2<96;k2++){
        float2 xv[4], wv[6];
        #pragma unroll
        for(int i=0;i<4;i++) xv[i]=As2[(ty+32*i)*97+k2];
        #pragma unroll
        for(int j=0;j<6;j++) wv[j]=w2s2[(tx+16*j)*97+k2];
        #pragma unroll
        for(int i=0;i<4;i++)
            #pragma unroll
            for(int j=0;j<6;j++){ acc[i][j]+=xv[i].x*wv[j].x; acc[i][j]+=xv[i].y*wv[j].y; }
    }
    __syncthreads();
    float* outs=S;            // 128*97
    #pragma unroll
    for(int i=0;i<4;i++){
        int p=ty+32*i;
        #pragma unroll
        for(int j=0;j<6;j++){
            int c=tx+16*j;
            outs[p*97+c]=acc[i][j];
        }
    }
    __syncthreads();
    float* op = out + ((size_t)b*16384 + pix0)*96;
    for(int i=tid;i<128*96;i+=512){
        int p=i/96, c=i%96;
        op[i]=outs[p*97+c];
    }
}

// ---------------- launch ----------------
extern "C" void kernel_launch(void* const* d_in, const int* in_sizes, int n_in,
                              void* d_out, int out_size){
    (void)in_sizes; (void)n_in; (void)out_size;
    const float* x   =(const float*)d_in[0];
    const float* w1  =(const float*)d_in[1];
    const float* s1  =(const float*)d_in[2];
    const float* b1  =(const float*)d_in[3];
    const float* cw0 =(const float*)d_in[4];
    const float* cw1 =(const float*)d_in[5];
    const float* cw2 =(const float*)d_in[6];
    const float* spw =(const float*)d_in[7];
    const float* bng =(const float*)d_in[8];
    const float* bnb =(const float*)d_in[9];
    const float* bnm =(const float*)d_in[10];
    const float* bnv =(const float*)d_in[11];
    const float* fc1 =(const float*)d_in[12];
    const float* msc =(const float*)d_in[13];
    const float* mbi =(const float*)d_in[14];
    const float* fc2 =(const float*)d_in[15];
    const float* w2  =(const float*)d_in[16];
    float* out=(float*)d_out;

    const int SM_PW1   = PW1_TOT*4;
    const int SM_FFT   = (SPEC+2048+64)*8;       // 83456
    const int SM_PW2   = PW2_TOT*4;              // ~174 KB
    const int SM_MLP   = MLP_TOT*4;

    cudaFuncSetAttribute(k_pw1,   cudaFuncAttributeMaxDynamicSharedMemorySize, SM_PW1);
    cudaFuncSetAttribute(k_fft,   cudaFuncAttributeMaxDynamicSharedMemorySize, SM_FFT);
    cudaFuncSetAttribute(k_pw2,   cudaFuncAttributeMaxDynamicSharedMemorySize, SM_PW2);
    cudaFuncSetAttribute(k_mlp,   cudaFuncAttributeMaxDynamicSharedMemorySize, SM_MLP);

    k_filt1<<<48, 256>>>(cw0, cw1, cw2);
    k_filt2<<<3*128*4, 128>>>();
    k_zero<<<1, 256>>>();
    k_pw1<<<dim3(128,Bb), 512, SM_PW1>>>(x, w1, s1, b1, spw, bng, bnb, bnm, bnv);
    k_mlp<<<1, 512, SM_MLP>>>(fc1, fc2, msc, mbi);
    k_fft<<<Bb*Mm, 512, SM_FFT>>>();
    k_pw2<<<dim3(128,Bb), 512, SM_PW2>>>(w2, out);
}

// round 7
// speedup vs baseline: 1.0989x; 1.0989x over previous
#include <cuda_runtime.h>
#include <math.h>

#define DINLINE __device__ __forceinline__

// ---------------- problem constants ----------------
#define Bb 8
#define Hh 128
#define Ww 128
#define Cc 96
#define Mm 192
#define SPEC (128*65)
#define INV_HW (1.0f/16384.0f)

// ---------------- device scratch ----------------
__device__ float  g_xpre[(size_t)Bb*Mm*Hh*Ww];     // reused in-place for xsp
__device__ float2 g_filt[(size_t)3*Mm*SPEC];       // resized filters (BR h order)
__device__ float2 g_tmp[(size_t)48*65*Mm];         // separable-resize intermediate
__device__ float  g_r[Bb*3*Mm];
__device__ float  g_stats[Bb*144];

extern __shared__ __align__(16) char SMEM[];

// ---------------- helpers ----------------
DINLINE int br7(int p){ return (int)(__brev((unsigned)p)>>25); }
DINLINE float2 cmulf(float2 a, float2 b){ return make_float2(a.x*b.x - a.y*b.y, a.x*b.y + a.y*b.x); }
DINLINE float2 f2add(float2 a,float2 b){ return make_float2(a.x+b.x, a.y+b.y); }
DINLINE float2 f2sub(float2 a,float2 b){ return make_float2(a.x-b.x, a.y-b.y); }
DINLINE float2 shflx(float2 v,int m){
    v.x = __shfl_xor_sync(0xffffffffu, v.x, m);
    v.y = __shfl_xor_sync(0xffffffffu, v.y, m);
    return v;
}
// packed f32x2 FMA (Blackwell)
DINLINE unsigned long long dup2(float x){
    unsigned long long r;
    asm("mov.b64 %0,{%1,%1};":"=l"(r):"f"(x));
    return r;
}
DINLINE void ffma2(unsigned long long& d, unsigned long long a, unsigned long long b){
    asm("fma.rn.f32x2 %0,%1,%2,%3;":"=l"(d):"l"(a),"l"(b),"l"(d));
}
DINLINE void unpk2(unsigned long long v, float& lo, float& hi){
    asm("mov.b64 {%0,%1},%2;":"=f"(lo),"=f"(hi):"l"(v));
}

// Forward DIF 128-pt FFT: natural input at p=j*32+lane -> X[br7(p)] at p.
DINLINE void fft128_dif(float2 z[4], const float2* tw, int lane){
    #pragma unroll
    for(int j=0;j<2;j++){
        int k=j*32+lane;
        float2 u=z[j], v=z[j+2];
        z[j]=f2add(u,v);
        z[j+2]=cmulf(f2sub(u,v), tw[k]);
    }
    {
        float2 w=tw[2*lane];
        float2 u=z[0],v=z[1];
        z[0]=f2add(u,v); z[1]=cmulf(f2sub(u,v),w);
        u=z[2]; v=z[3];
        z[2]=f2add(u,v); z[3]=cmulf(f2sub(u,v),w);
    }
    #pragma unroll
    for(int d=16; d>=1; d>>=1){
        int k=lane&(d-1);
        float2 w=tw[k*(64/d)];
        bool up=(lane&d)!=0;
        #pragma unroll
        for(int j=0;j<4;j++){
            float2 o=shflx(z[j],d);
            float2 r;
            if(up) r=cmulf(make_float2(o.x - z[j].x, o.y - z[j].y), w);
            else   r=make_float2(z[j].x+o.x, z[j].y+o.y);
            z[j]=r;
        }
    }
}

// DIT 128-pt FFT: bit-reversed input at p -> natural output at p.
template<bool CONJ>
DINLINE void fft128_dit(float2 z[4], const float2* tw, int lane){
    #pragma unroll
    for(int d=1; d<=16; d<<=1){
        int k=lane&(d-1);
        float2 w=tw[k*(64/d)];
        if(CONJ) w.y=-w.y;
        bool up=(lane&d)!=0;
        #pragma unroll
        for(int j=0;j<4;j++){
            float2 o=shflx(z[j],d);
            float2 r;
            if(up){
                float2 t=cmulf(w, z[j]);
                r=make_float2(o.x-t.x, o.y-t.y);
            } else {
                float2 t=cmulf(w, o);
                r=make_float2(z[j].x+t.x, z[j].y+t.y);
            }
            z[j]=r;
        }
    }
    {
        float2 w=tw[2*lane]; if(CONJ) w.y=-w.y;
        float2 t=cmulf(w,z[1]); float2 u=z[0];
        z[0]=f2add(u,t); z[1]=f2sub(u,t);
        t=cmulf(w,z[3]); u=z[2];
        z[2]=f2add(u,t); z[3]=f2sub(u,t);
    }
    #pragma unroll
    for(int j=0;j<2;j++){
        int k=j*32+lane;
        float2 w=tw[k]; if(CONJ) w.y=-w.y;
        float2 t=cmulf(w,z[j+2]); float2 u=z[j];
        z[j]=f2add(u,t);
        z[j+2]=f2sub(u,t);
    }
}

// ---------------- bicubic resize taps (match reference) ----------------
DINLINE double cubicw(double t){
    t = fabs(t);
    const double a = -0.75;
    if(t <= 1.0) return ((a+2.0)*t - (a+3.0))*t*t + 1.0;
    if(t <  2.0) return a*(((t-5.0)*t+8.0)*t-4.0);
    return 0.0;
}
DINLINE void taps4(int j, int oldn, int newn, int* idx, float* wt){
    double s = (newn > 1) ? (double)j * (double)(oldn-1) / (double)(newn-1) : 0.0;
    int f = (int)floor(s);
    #pragma unroll
    for(int k=0;k<4;k++){
        int kk = f + k - 1;
        idx[k] = min(max(kk, 0), oldn-1);
        wt[k]  = (float)cubicw(s - (double)kk);
    }
}

// scale tables
__constant__ int c_SH[3]={16,8,24};
__constant__ int c_SW[3]={9,4,13};
__constant__ int c_RB[3]={0,16,24};   // row base in g_tmp

// ---------------- k_filt1: W-resize, one block per source row ----------------
__global__ void __launch_bounds__(256) k_filt1(const float* __restrict__ cw0,
                                               const float* __restrict__ cw1,
                                               const float* __restrict__ cw2){
    __shared__ int   widx[65][4];
    __shared__ float wwt [65][4];
    __shared__ float2 rowb[13*Mm];    // max ow=13
    int r = blockIdx.x;               // 0..47
    int s = (r<16)?0:((r<24)?1:2);
    int ih = r - c_RB[s];
    int ow = c_SW[s];
    const float* cws = (s==0)?cw0:((s==1)?cw1:cw2);
    int tid=threadIdx.x;
    if(tid<65) taps4(tid, ow, 65, widx[tid], wwt[tid]);
    const float2* src = (const float2*)(cws) + (size_t)ih*ow*Mm;
    for(int i=tid;i<ow*Mm;i+=256) rowb[i]=src[i];
    __syncthreads();
    float2* dst = g_tmp + (size_t)r*65*Mm;
    for(int e=tid;e<65*Mm;e+=256){
        int w=e/Mm, m=e%Mm;
        float ax=0.f, ay=0.f;
        #pragma unroll
        for(int a=0;a<4;a++){
            float wg=wwt[w][a];
            float2 v=rowb[widx[w][a]*Mm+m];
            ax+=wg*v.x; ay+=wg*v.y;
        }
        dst[e]=make_float2(ax,ay);
    }
}

// ---------------- k_filt2: H-resize + transpose into [s][m][BRh*65+w] ----------------
__global__ void __launch_bounds__(128) k_filt2(){
    __shared__ int   hidx[4];
    __shared__ float hwt [4];
    __shared__ float2 tile[48*65];    // [mm][w]
    int bid=blockIdx.x;               // 3*128*4
    int s  = bid/512;
    int rem= bid%512;
    int hq = rem/4;
    int m0 = (rem%4)*48;
    int tid=threadIdx.x;
    if(tid==0){
        int id[4]; float wt[4];
        taps4(hq, c_SH[s], 128, id, wt);
        #pragma unroll
        for(int a=0;a<4;a++){ hidx[a]=id[a]; hwt[a]=wt[a]; }
    }
    __syncthreads();
    const float2* base = g_tmp + (size_t)c_RB[s]*65*Mm;
    for(int e=tid;e<65*48;e+=128){
        int w=e/48, mm=e%48;
        int m=m0+mm;
        float ax=0.f, ay=0.f;
        #pragma unroll
        for(int a=0;a<4;a++){
            float2 v=base[(size_t)hidx[a]*65*Mm + w*Mm + m];
            ax+=hwt[a]*v.x; ay+=hwt[a]*v.y;
        }
        tile[mm*65+w]=make_float2(ax,ay);
    }
    __syncthreads();
    int hb=br7(hq);
    for(int e=tid;e<48*65;e+=128){
        int mm=e/65, w=e%65;
        g_filt[(size_t)(s*Mm+m0+mm)*SPEC + hb*65 + w]=tile[mm*65+w];
    }
}

// ---------------- k_zero ----------------
__global__ void k_zero(){
    for(int i=threadIdx.x;i<Bb*144;i+=blockDim.x) g_stats[i]=0.f;
}

// ---------------- k_pw1: fused pwconv1+Soa + routing stats (512 thr, FFMA2) ----------------
// smem: xs[128*97], ws_k[96*194] (k-major, m pairs), sws[48*97], bnp[96], red[48*33]
#define PW1_XS   0
#define PW1_WS   (PW1_XS+12416)
#define PW1_SWS  (PW1_WS+96*194)
#define PW1_BNP  (PW1_SWS+4656)
#define PW1_RED  (PW1_BNP+96)
#define PW1_TOT  (PW1_RED+1584)
__global__ void __launch_bounds__(512) k_pw1(const float* __restrict__ x,
                                             const float* __restrict__ w1,
                                             const float* __restrict__ s1,
                                             const float* __restrict__ b1,
                                             const float* __restrict__ spw,
                                             const float* __restrict__ bng,
                                             const float* __restrict__ bnb,
                                             const float* __restrict__ bnm,
                                             const float* __restrict__ bnv){
    float* S=(float*)SMEM;
    float* xs  = S+PW1_XS;
    float* ws  = S+PW1_WS;     // [k][194] k-major
    float* sws = S+PW1_SWS;
    float* bnp = S+PW1_BNP;
    float* red = S+PW1_RED;
    int tid=threadIdx.x;
    int b=blockIdx.y, pix0=blockIdx.x*128;
    const float* xb = x + ((size_t)b*16384 + pix0)*96;
    for(int i=tid;i<128*96;i+=512){ int p=i/96,c=i%96; xs[p*97+c]=xb[i]; }
    for(int i=tid;i<192*96;i+=512){ int m=i/96,k=i%96; ws[k*194+m]=w1[i]; }
    for(int i=tid;i<48*96;i+=512){ int sc=i/96,c=i%96; sws[sc*97+c]=spw[i]; }
    if(tid<48){
        float sc=rsqrtf(bnv[tid]+1e-5f)*bng[tid];
        bnp[tid]=sc;
        bnp[48+tid]=bnb[tid]-bnm[tid]*sc;
    }
    __syncthreads();
    int tx=tid&15, ty=tid>>4;    // ty 0..31 -> 4 pixels each; tx -> m pairs 2tx+32j
    const unsigned long long* ws2 = (const unsigned long long*)ws;   // [k][97] pairs
    unsigned long long acc[4][6];
    float acc2[4][3];
    #pragma unroll
    for(int i=0;i<4;i++){
        #pragma unroll
        for(int j=0;j<6;j++) acc[i][j]=0ull;
        #pragma unroll
        for(int j=0;j<3;j++) acc2[i][j]=0.f;
    }
    for(int k=0;k<96;k++){
        unsigned long long xd[4], wv[6];
        float xv[4], wv2[3];
        #pragma unroll
        for(int i=0;i<4;i++){ xv[i]=xs[(ty+32*i)*97+k]; xd[i]=dup2(xv[i]); }
        #pragma unroll
        for(int j=0;j<6;j++) wv[j]=ws2[k*97 + tx+16*j];
        #pragma unroll
        for(int j=0;j<3;j++) wv2[j]=sws[(tx*3+j)*97+k];
        #pragma unroll
        for(int i=0;i<4;i++){
            #pragma unroll
            for(int j=0;j<6;j++) ffma2(acc[i][j], xd[i], wv[j]);
            #pragma unroll
            for(int j=0;j<3;j++) acc2[i][j]+=xv[i]*wv2[j];
        }
    }
    // sctx partials
    #pragma unroll
    for(int j=0;j<3;j++){
        int sc=tx*3+j;
        float scale=bnp[sc], shift=bnp[48+sc];
        float ssum=0.f;
        #pragma unroll
        for(int i=0;i<4;i++) ssum+=fmaxf(acc2[i][j]*scale+shift,0.f);
        red[sc*33+ty]=ssum;
    }
    // gctx
    float gsum=0.f;
    if(tid<96){
        #pragma unroll 4
        for(int p=0;p<128;p++) gsum+=xs[p*97+tid];
    }
    float scb=*s1, bib=*b1;
    __syncthreads();
    if(tid<96) atomicAdd(&g_stats[b*144+tid], gsum);
    if(tid<48){
        float ssum=0.f;
        #pragma unroll
        for(int t=0;t<32;t++) ssum+=red[tid*33+t];
        atomicAdd(&g_stats[b*144+96+tid], ssum);
    }
    float* outs = S;          // reuse: 192*129 = 24768 < PW1_TOT
    #pragma unroll
    for(int i=0;i<4;i++){
        int p=ty+32*i;
        #pragma unroll
        for(int j=0;j<6;j++){
            int m0=2*tx+32*j;
            float lo,hi;
            unpk2(acc[i][j], lo, hi);
            float rl=fmaxf(lo,0.f), rh=fmaxf(hi,0.f);
            outs[m0*129+p]    =scb*rl*rl+bib;
            outs[(m0+1)*129+p]=scb*rh*rh+bib;
        }
    }
    __syncthreads();
    float* op = g_xpre + (size_t)b*Mm*16384 + pix0;
    for(int i=tid;i<192*128;i+=512){
        int mm=i>>7, p=i&127;
        op[(size_t)mm*16384+p]=outs[mm*129+p];
    }
}

// ---------------- k_mlp ----------------
#define MLP_SF   0
#define MLP_FC1  (8*145)
#define MLP_HM   (MLP_FC1+36*145)
#define MLP_FC2  (MLP_HM+8*37)
#define MLP_TOT  (MLP_FC2+576*37)
__global__ void __launch_bounds__(512) k_mlp(const float* __restrict__ fc1,
                                             const float* __restrict__ fc2,
                                             const float* __restrict__ msc,
                                             const float* __restrict__ mbi){
    float* S=(float*)SMEM;
    float* sf  = S+MLP_SF;
    float* f1s = S+MLP_FC1;
    float* hm  = S+MLP_HM;
    float* f2s = S+MLP_FC2;
    int tid=threadIdx.x;
    for(int i=tid;i<8*144;i+=512){ int b=i/144,k=i%144; sf[b*145+k]=g_stats[i]*(1.f/16384.f); }
    for(int i=tid;i<36*144;i+=512){ int j=i/144,k=i%144; f1s[j*145+k]=fc1[i]; }
    for(int i=tid;i<576*36;i+=512){ int j=i/36,k=i%36; f2s[j*37+k]=fc2[i]; }
    __syncthreads();
    if(tid<288){
        int b=tid/36, j=tid%36;
        float a=0.f;
        #pragma unroll 8
        for(int k=0;k<144;k++) a+=sf[b*145+k]*f1s[j*145+k];
        float r=fmaxf(a,0.f);
        hm[b*37+j]=(*msc)*r*r + (*mbi);
    }
    __syncthreads();
    for(int idx=tid; idx<8*Mm; idx+=512){
        int b=idx/Mm, m=idx%Mm;
        float lg[3];
        #pragma unroll
        for(int s=0;s<3;s++){
            float a=0.f;
            const float* f2=f2s+(size_t)(s*Mm+m)*37;
            #pragma unroll
            for(int k=0;k<36;k++) a+=hm[b*37+k]*f2[k];
            lg[s]=a;
        }
        float mx=fmaxf(lg[0],fmaxf(lg[1],lg[2]));
        float e0=expf(lg[0]-mx), e1=expf(lg[1]-mx), e2=expf(lg[2]-mx);
        float inv=1.f/(e0+e1+e2);
        g_r[(b*3+0)*Mm+m]=e0*inv;
        g_r[(b*3+1)*Mm+m]=e1*inv;
        g_r[(b*3+2)*Mm+m]=e2*inv;
    }
}

// ---------------- k_fft (512 thr) ----------------
__global__ void __launch_bounds__(512) k_fft(){
    float2* sh=(float2*)SMEM;
    float2* sm = sh;                 // 8320
    float2* tmpAll = sh + SPEC;      // 16*128
    float2* tw = sh + SPEC + 2048;   // 64
    int tid=threadIdx.x, lane=tid&31, wid=tid>>5;   // 16 warps
    int bm=blockIdx.x;
    int b=bm/Mm, m=bm%Mm;
    float* plane = g_xpre + (size_t)bm*16384;
    if(tid<64){
        float s,c;
        sincospif((float)tid*(1.0f/64.0f), &s, &c);
        tw[tid]=make_float2(c,-s);
    }
    __syncthreads();
    float2* tmp = tmpAll + wid*128;
    // Phase A: forward row rFFTs
    for(int pr=wid; pr<64; pr+=16){
        int ra=2*pr, rb=ra+1;
        float2 z[4];
        #pragma unroll
        for(int j=0;j<4;j++){
            int p=j*32+lane, q=br7(p);
            z[j]=make_float2(plane[ra*128+q], plane[rb*128+q]);
        }
        fft128_dit<false>(z,tw,lane);
        #pragma unroll
        for(int j=0;j<4;j++) tmp[j*32+lane]=z[j];
        __syncwarp();
        #pragma unroll
        for(int t=0;t<2;t++){
            int k=t*32+lane;
            float2 Zk=tmp[k], Zc=tmp[(128-k)&127];
            sm[ra*65+k]=make_float2(0.5f*(Zk.x+Zc.x), 0.5f*(Zk.y-Zc.y));
            sm[rb*65+k]=make_float2(0.5f*(Zk.y+Zc.y), 0.5f*(Zc.x-Zk.x));
        }
        if(lane==0){
            float2 Zk=tmp[64];
            sm[ra*65+64]=make_float2(Zk.x,0.f);
            sm[rb*65+64]=make_float2(Zk.y,0.f);
        }
        __syncwarp();
    }
    __syncthreads();
    // Phase B: forward column FFTs (natural -> BR h)
    for(int col=wid; col<65; col+=16){
        float2 z[4];
        #pragma unroll
        for(int j=0;j<4;j++) z[j]=sm[(j*32+lane)*65+col];
        fft128_dif(z,tw,lane);
        #pragma unroll
        for(int j=0;j<4;j++) sm[(j*32+lane)*65+col]=z[j];
    }
    __syncthreads();
    // Phase C: routed filter multiply
    {
        float r0=g_r[(b*3+0)*Mm+m], r1=g_r[(b*3+1)*Mm+m], r2=g_r[(b*3+2)*Mm+m];
        const float2* f0=g_filt + (size_t)(0*Mm+m)*SPEC;
        const float2* f1=g_filt + (size_t)(1*Mm+m)*SPEC;
        const float2* f2=g_filt + (size_t)(2*Mm+m)*SPEC;
        for(int e=tid;e<SPEC;e+=512){
            float2 a=f0[e], bb=f1[e], c=f2[e];
            float2 comb=make_float2(a.x*r0+bb.x*r1+c.x*r2, a.y*r0+bb.y*r1+c.y*r2);
            sm[e]=cmulf(sm[e],comb);
        }
    }
    __syncthreads();
    // Phase D: inverse column FFTs
    for(int col=wid; col<65; col+=16){
        float2 z[4];
        #pragma unroll
        for(int j=0;j<4;j++) z[j]=sm[(j*32+lane)*65+col];
        fft128_dit<true>(z,tw,lane);
        #pragma unroll
        for(int j=0;j<4;j++) sm[(j*32+lane)*65+col]=z[j];
    }
    __syncthreads();
    // Phase E: inverse row rFFTs
    for(int pr=wid; pr<64; pr+=16){
        int ra=2*pr, rb=ra+1;
        float2 z[4];
        #pragma unroll
        for(int j=0;j<4;j++){
            int p=j*32+lane, k=br7(p);
            float2 zz;
            if(k<=64){
                float2 a=sm[ra*65+k], bb=sm[rb*65+k];
                if(k==0||k==64){ a.y=0.f; bb.y=0.f; }
                zz=make_float2(a.x-bb.y, a.y+bb.x);
            } else {
                int kk=128-k;
                float2 a=sm[ra*65+kk], bb=sm[rb*65+kk];
                zz=make_float2(a.x+bb.y, bb.x-a.y);
            }
            z[j]=zz;
        }
        fft128_dit<true>(z,tw,lane);
        #pragma unroll
        for(int j=0;j<4;j++){
            int p=j*32+lane;
            plane[ra*128+p]=z[j].x*INV_HW;
            plane[rb*128+p]=z[j].y*INV_HW;
        }
    }
}

// ---------------- k_pw2 (512 thr, FFMA2, m-major weights) ----------------
// smem: As[192*129]=24768, w2m[192*98]=18816 (m-major, c pairs)
#define PW2_AS   0
#define PW2_W2   (PW2_AS+24768)
#define PW2_TOT  (PW2_W2+192*98)
__global__ void __launch_bounds__(512) k_pw2(const float* __restrict__ w2,
                                             float* __restrict__ out){
    float* S=(float*)SMEM;
    float* As  = S+PW2_AS;     // [m][129]
    float* w2m = S+PW2_W2;     // [m][98] c-contiguous
    int tid=threadIdx.x;
    int b=blockIdx.y, pix0=blockIdx.x*128;
    const float* ap = g_xpre + (size_t)b*Mm*16384 + pix0;
    for(int i=tid;i<192*128;i+=512){
        int mm=i>>7, p=i&127;
        As[mm*129+p]=ap[(size_t)mm*16384+p];
    }
    for(int i=tid;i<96*192;i+=512){
        int c=i/192, m=i%192;
        w2m[m*98+c]=w2[i];
    }
    __syncthreads();
    int tx=tid&15, ty=tid>>4;    // ty 0..31; c pairs 2tx+32j, j=0..2
    const unsigned long long* w2p=(const unsigned long long*)w2m;   // [m][49]
    unsigned long long acc[4][3];
    #pragma unroll
    for(int i=0;i<4;i++)
        #pragma unroll
        for(int j=0;j<3;j++) acc[i][j]=0ull;
    for(int m=0;m<192;m++){
        unsigned long long xd[4], wv[3];
        #pragma unroll
        for(int i=0;i<4;i++) xd[i]=dup2(As[m*129 + ty+32*i]);
        #pragma unroll
        for(int j=0;j<3;j++) wv[j]=w2p[m*49 + tx+16*j];
        #pragma unroll
        for(int i=0;i<4;i++)
            #pragma unroll
            for(int j=0;j<3;j++) ffma2(acc[i][j], xd[i], wv[j]);
    }
    __syncthreads();
    float* outs=S;            // 128*97
    #pragma unroll
    for(int i=0;i<4;i++){
        int p=ty+32*i;
        #pragma unroll
        for(int j=0;j<3;j++){
            int c0=2*tx+32*j;
            float lo,hi;
            unpk2(acc[i][j], lo, hi);
            outs[p*97+c0]=lo;
            outs[p*97+c0+1]=hi;
        }
    }
    __syncthreads();
    float* op = out + ((size_t)b*16384 + pix0)*96;
    for(int i=tid;i<128*96;i+=512){
        int p=i/96, c=i%96;
        op[i]=outs[p*97+c];
    }
}

// ---------------- launch ----------------
extern "C" void kernel_launch(void* const* d_in, const int* in_sizes, int n_in,
                              void* d_out, int out_size){
    (void)in_sizes; (void)n_in; (void)out_size;
    const float* x   =(const float*)d_in[0];
    const float* w1  =(const float*)d_in[1];
    const float* s1  =(const float*)d_in[2];
    const float* b1  =(const float*)d_in[3];
    const float* cw0 =(const float*)d_in[4];
    const float* cw1 =(const float*)d_in[5];
    const float* cw2 =(const float*)d_in[6];
    const float* spw =(const float*)d_in[7];
    const float* bng =(const float*)d_in[8];
    const float* bnb =(const float*)d_in[9];
    const float* bnm =(const float*)d_in[10];
    const float* bnv =(const float*)d_in[11];
    const float* fc1 =(const float*)d_in[12];
    const float* msc =(const float*)d_in[13];
    const float* mbi =(const float*)d_in[14];
    const float* fc2 =(const float*)d_in[15];
    const float* w2  =(const float*)d_in[16];
    float* out=(float*)d_out;

    const int SM_PW1   = PW1_TOT*4;              // ~150 KB
    const int SM_FFT   = (SPEC+2048+64)*8;       // 83456
    const int SM_PW2   = PW2_TOT*4;              // ~174 KB
    const int SM_MLP   = MLP_TOT*4;

    cudaFuncSetAttribute(k_pw1,   cudaFuncAttributeMaxDynamicSharedMemorySize, SM_PW1);
    cudaFuncSetAttribute(k_fft,   cudaFuncAttributeMaxDynamicSharedMemorySize, SM_FFT);
    cudaFuncSetAttribute(k_pw2,   cudaFuncAttributeMaxDynamicSharedMemorySize, SM_PW2);
    cudaFuncSetAttribute(k_mlp,   cudaFuncAttributeMaxDynamicSharedMemorySize, SM_MLP);

    k_filt1<<<48, 256>>>(cw0, cw1, cw2);
    k_filt2<<<3*128*4, 128>>>();
    k_zero<<<1, 256>>>();
    k_pw1<<<dim3(128,Bb), 512, SM_PW1>>>(x, w1, s1, b1, spw, bng, bnb, bnm, bnv);
    k_mlp<<<1, 512, SM_MLP>>>(fc1, fc2, msc, mbi);
    k_fft<<<Bb*Mm, 512, SM_FFT>>>();
    k_pw2<<<dim3(128,Bb), 512, SM_PW2>>>(w2, out);
}